// round 3
// baseline (speedup 1.0000x reference)
#include <cuda_runtime.h>
#include <cuda_bf16.h>
#include <math.h>

// Problem constants
#define NTOK   8192
#define DIM    256
#define HH     8
#define HD     32
#define WW     64
#define NW     128          // NTOK / WW
#define T6     216          // 3*40 + 3*32
#define QSCALE 0.17677669529663687f   // 32^-0.5

// Global scratch (static device allocations -- allowed)
__device__ float g_q[NTOK * DIM];
__device__ float g_k[NTOK * DIM];
__device__ float g_v[NTOK * DIM];
__device__ float g_att[NTOK * DIM];

// ---------------------------------------------------------------------------
// QKV GEMM: qkv = feats[8192,256] @ qkv_w^T[256,768] + b -> split q(scaled)/k/v
// BM=64 BN=64 BK=16, 256 threads, 4x4 per thread.
// ---------------------------------------------------------------------------
__global__ __launch_bounds__(256) void qkv_gemm_kernel(
    const float* __restrict__ A, const float* __restrict__ Wt,
    const float* __restrict__ bias)
{
    __shared__ float As[16][68];
    __shared__ float Bs[16][68];
    const int m0 = blockIdx.x * 64, n0 = blockIdx.y * 64;
    const int tid = threadIdx.x;
    const int tx = tid & 15, ty = tid >> 4;
    const int lr = tid >> 2, lk = (tid & 3) << 2;

    float c[4][4] = {};

    for (int kk = 0; kk < 256; kk += 16) {
        float4 a4 = *(const float4*)&A [(m0 + lr) * 256 + kk + lk];
        float4 b4 = *(const float4*)&Wt[(n0 + lr) * 256 + kk + lk];
        As[lk + 0][lr] = a4.x; As[lk + 1][lr] = a4.y;
        As[lk + 2][lr] = a4.z; As[lk + 3][lr] = a4.w;
        Bs[lk + 0][lr] = b4.x; Bs[lk + 1][lr] = b4.y;
        Bs[lk + 2][lr] = b4.z; Bs[lk + 3][lr] = b4.w;
        __syncthreads();
#pragma unroll
        for (int k = 0; k < 16; k++) {
            float4 av = *(const float4*)&As[k][ty * 4];
            float4 bv = *(const float4*)&Bs[k][tx * 4];
            float aa[4] = {av.x, av.y, av.z, av.w};
            float bb[4] = {bv.x, bv.y, bv.z, bv.w};
#pragma unroll
            for (int i = 0; i < 4; i++)
#pragma unroll
                for (int j = 0; j < 4; j++)
                    c[i][j] += aa[i] * bb[j];
        }
        __syncthreads();
    }

#pragma unroll
    for (int i = 0; i < 4; i++) {
        int m = m0 + ty * 4 + i;
        int n = n0 + tx * 4;
        int s = n >> 8;            // 0=q 1=k 2=v (64-col tile never crosses)
        int col = n & 255;
        float4 b4 = *(const float4*)&bias[n];
        float4 o;
        o.x = c[i][0] + b4.x; o.y = c[i][1] + b4.y;
        o.z = c[i][2] + b4.z; o.w = c[i][3] + b4.w;
        float* dst;
        if (s == 0) {
            o.x *= QSCALE; o.y *= QSCALE; o.z *= QSCALE; o.w *= QSCALE;
            dst = g_q;
        } else if (s == 1) dst = g_k;
        else               dst = g_v;
        *(float4*)&dst[m * 256 + col] = o;
    }
}

// ---------------------------------------------------------------------------
// Projection GEMM: out = g_att[8192,256] @ proj_w^T[256,256] + proj_b
// ---------------------------------------------------------------------------
__global__ __launch_bounds__(256) void proj_gemm_kernel(
    const float* __restrict__ Wt, const float* __restrict__ bias,
    float* __restrict__ out)
{
    __shared__ float As[16][68];
    __shared__ float Bs[16][68];
    const int m0 = blockIdx.x * 64, n0 = blockIdx.y * 64;
    const int tid = threadIdx.x;
    const int tx = tid & 15, ty = tid >> 4;
    const int lr = tid >> 2, lk = (tid & 3) << 2;

    float c[4][4] = {};

    for (int kk = 0; kk < 256; kk += 16) {
        float4 a4 = *(const float4*)&g_att[(m0 + lr) * 256 + kk + lk];
        float4 b4 = *(const float4*)&Wt  [(n0 + lr) * 256 + kk + lk];
        As[lk + 0][lr] = a4.x; As[lk + 1][lr] = a4.y;
        As[lk + 2][lr] = a4.z; As[lk + 3][lr] = a4.w;
        Bs[lk + 0][lr] = b4.x; Bs[lk + 1][lr] = b4.y;
        Bs[lk + 2][lr] = b4.z; Bs[lk + 3][lr] = b4.w;
        __syncthreads();
#pragma unroll
        for (int k = 0; k < 16; k++) {
            float4 av = *(const float4*)&As[k][ty * 4];
            float4 bv = *(const float4*)&Bs[k][tx * 4];
            float aa[4] = {av.x, av.y, av.z, av.w};
            float bb[4] = {bv.x, bv.y, bv.z, bv.w};
#pragma unroll
            for (int i = 0; i < 4; i++)
#pragma unroll
                for (int j = 0; j < 4; j++)
                    c[i][j] += aa[i] * bb[j];
        }
        __syncthreads();
    }

#pragma unroll
    for (int i = 0; i < 4; i++) {
        int m = m0 + ty * 4 + i;
        int n = n0 + tx * 4;
        float4 b4 = *(const float4*)&bias[n];
        float4 o;
        o.x = c[i][0] + b4.x; o.y = c[i][1] + b4.y;
        o.z = c[i][2] + b4.z; o.w = c[i][3] + b4.w;
        *(float4*)&out[m * 256 + n] = o;
    }
}

// ---------------------------------------------------------------------------
// Attention kernel: one block per (window, head). 256 threads.
// Shared layout (floats), total 46336 floats = 185344 B:
//   scw   [64*6]      @ 0
//   sq    [64*36]     @ 384      (stride 36)
//   sk    [64*36]     @ 2688
//   svT   [32*68]     @ 4992     (d-major, stride 68)
//   stab  [216*32]    @ 7168     (q-table, then k-table; dead after Dq/Dk)
//   rgnA  [64*220]    @ 14080    (Dq stride 217; later at-bins stride 220)
//   rgnB  [64*220]    @ 28160    (Dk stride 217; later vtabT 32x, stride 220)
//   slog  [64*64]     @ 42240
// ---------------------------------------------------------------------------
#define SM_FLOATS 46336
#define SMEM_BYTES (SM_FLOATS * 4)

__global__ __launch_bounds__(256) void attn_kernel(
    const float* __restrict__ n_coords,
    const float* __restrict__ qx, const float* __restrict__ kx,
    const float* __restrict__ vx,
    const float* __restrict__ qr, const float* __restrict__ kr,
    const float* __restrict__ vr)
{
    extern __shared__ float sm[];
    float* scw  = sm;
    float* sq   = sm + 384;
    float* sk   = sm + 2688;
    float* svT  = sm + 4992;
    float* stab = sm + 7168;
    float* sdq  = sm + 14080;   // stride 217
    float* sdk  = sm + 28160;   // stride 217
    float* slog = sm + 42240;
    float* sat   = sdq;         // stride 220 (aliases Dq after logits)
    float* vtabT = sdk;         // 32 rows, stride 220 (aliases Dk)

    const int nb = blockIdx.x, h = blockIdx.y;
    const int tid = threadIdx.x;
    const int l = tid & 31, w = tid >> 5;
    const int tok0 = nb * WW;

    // ---- load coords, q, k, v(T), q-table ----
    for (int s = tid; s < WW * 6; s += 256) {
        int i = s / 6, c = s % 6;
        scw[s] = n_coords[(tok0 + i) * 6 + c] * (c < 3 ? 4.0f : 8.0f);
    }
    for (int s = tid; s < WW * HD; s += 256) {
        int i = s >> 5, d = s & 31;
        int g = (tok0 + i) * 256 + h * 32 + d;
        sq[i * 36 + d]  = g_q[g];
        sk[i * 36 + d]  = g_k[g];
        svT[d * 68 + i] = g_v[g];
    }
    for (int s = tid; s < T6 * HD; s += 256) {
        int t = s >> 5, d = s & 31;
        stab[s] = (t < 120) ? qx[(t * 8 + h) * 32 + d]
                            : qr[((t - 120) * 8 + h) * 32 + d];
    }
    __syncthreads();

    // ---- Dq[i][t] = q_i . qtab[t]  (lanes share t -> broadcast LDS) ----
    {
        int i = tid & 63, grp = tid >> 6;
        float4 q4[8];
        const float4* sq4 = (const float4*)(sq + i * 36);
#pragma unroll
        for (int d4 = 0; d4 < 8; d4++) q4[d4] = sq4[d4];
        const float4* st4 = (const float4*)stab;
        for (int t = grp * 54; t < grp * 54 + 54; t++) {
            float acc = 0.f;
#pragma unroll
            for (int d4 = 0; d4 < 8; d4++) {
                float4 tv = st4[t * 8 + d4];
                acc += q4[d4].x * tv.x + q4[d4].y * tv.y
                     + q4[d4].z * tv.z + q4[d4].w * tv.w;
            }
            sdq[i * 217 + t] = acc;
        }
    }
    __syncthreads();

    // ---- load k-table, compute Dk ----
    for (int s = tid; s < T6 * HD; s += 256) {
        int t = s >> 5, d = s & 31;
        stab[s] = (t < 120) ? kx[(t * 8 + h) * 32 + d]
                            : kr[((t - 120) * 8 + h) * 32 + d];
    }
    __syncthreads();
    {
        int i = tid & 63, grp = tid >> 6;
        float4 k4[8];
        const float4* sk4 = (const float4*)(sk + i * 36);
#pragma unroll
        for (int d4 = 0; d4 < 8; d4++) k4[d4] = sk4[d4];
        const float4* st4 = (const float4*)stab;
        for (int t = grp * 54; t < grp * 54 + 54; t++) {
            float acc = 0.f;
#pragma unroll
            for (int d4 = 0; d4 < 8; d4++) {
                float4 tv = st4[t * 8 + d4];
                acc += k4[d4].x * tv.x + k4[d4].y * tv.y
                     + k4[d4].z * tv.z + k4[d4].w * tv.w;
            }
            sdk[i * 217 + t] = acc;
        }
    }
    __syncthreads();

    // ---- logits: qk + bias gathers ----
    {
        const int basec[6] = {0, 40, 80, 120, 152, 184};
        const int offc[6]  = {20, 20, 20, 16, 16, 16};
        const int hic[6]   = {39, 39, 39, 31, 31, 31};
        for (int r = 0; r < 8; r++) {
            int i = w * 8 + r;
            float ci[6];
#pragma unroll
            for (int c = 0; c < 6; c++) ci[c] = scw[i * 6 + c];
            const float4* sq4 = (const float4*)(sq + i * 36);
#pragma unroll
            for (int jj = 0; jj < 2; jj++) {
                int j = l + jj * 32;
                float acc = 0.f;
                const float4* sk4 = (const float4*)(sk + j * 36);
#pragma unroll
                for (int d4 = 0; d4 < 8; d4++) {
                    float4 a = sq4[d4], b = sk4[d4];
                    acc += a.x * b.x + a.y * b.y + a.z * b.z + a.w * b.w;
                }
#pragma unroll
                for (int c = 0; c < 6; c++) {
                    int id = (int)floorf(ci[c] - scw[j * 6 + c]) + offc[c];
                    id = min(max(id, 0), hic[c]);
                    int t = basec[c] + id;
                    acc += sdq[i * 217 + t] + sdk[j * 217 + t];
                }
                slog[i * 64 + j] = acc;
            }
        }
    }

    // ---- softmax (rows owned per-warp; no inter-warp dep) ----
    for (int r = 0; r < 8; r++) {
        int i = w * 8 + r;
        float v0 = slog[i * 64 + l], v1 = slog[i * 64 + l + 32];
        float m = fmaxf(v0, v1);
#pragma unroll
        for (int o = 16; o > 0; o >>= 1)
            m = fmaxf(m, __shfl_xor_sync(0xffffffffu, m, o));
        float e0 = __expf(v0 - m), e1 = __expf(v1 - m);
        float s = e0 + e1;
#pragma unroll
        for (int o = 16; o > 0; o >>= 1)
            s += __shfl_xor_sync(0xffffffffu, s, o);
        float inv = 1.0f / s;
        slog[i * 64 + l]      = e0 * inv;
        slog[i * 64 + l + 32] = e1 * inv;
    }
    __syncthreads();   // everyone done reading Dq/Dk before aliasing

    // ---- zero bins, load v-table (transposed) ----
    for (int s = tid; s < 64 * 220; s += 256) sat[s] = 0.f;
    for (int s = tid; s < T6 * HD; s += 256) {
        int t = s >> 5, d = s & 31;
        float val = (t < 120) ? vx[(t * 8 + h) * 32 + d]
                              : vr[((t - 120) * 8 + h) * 32 + d];
        vtabT[d * 220 + t] = val;
    }
    __syncthreads();

    // ---- bin attn into at[i][t6] (shared atomics) ----
    {
        const int basec[6] = {0, 40, 80, 120, 152, 184};
        const int offc[6]  = {20, 20, 20, 16, 16, 16};
        const int hic[6]   = {39, 39, 39, 31, 31, 31};
        for (int r = 0; r < 8; r++) {
            int i = w * 8 + r;
            float ci[6];
#pragma unroll
            for (int c = 0; c < 6; c++) ci[c] = scw[i * 6 + c];
#pragma unroll
            for (int jj = 0; jj < 2; jj++) {
                int j = l + jj * 32;
                float a = slog[i * 64 + j];
#pragma unroll
                for (int c = 0; c < 6; c++) {
                    int id = (int)floorf(ci[c] - scw[j * 6 + c]) + offc[c];
                    id = min(max(id, 0), hic[c]);
                    atomicAdd(&sat[i * 220 + basec[c] + id], a);
                }
            }
        }
    }
    __syncthreads();

    // ---- out[i][d] = attn @ v  +  at @ vtab ;  lane = d ----
    for (int r = 0; r < 8; r++) {
        int i = w * 8 + r;
        float acc = 0.f;
        const float4* at4 = (const float4*)(slog + i * 64);
        const float4* sv4 = (const float4*)(svT + l * 68);
#pragma unroll
        for (int j4 = 0; j4 < 16; j4++) {
            float4 a = at4[j4], vv = sv4[j4];
            acc += a.x * vv.x + a.y * vv.y + a.z * vv.z + a.w * vv.w;
        }
        const float4* sb4 = (const float4*)(sat + i * 220);
        const float4* vt4 = (const float4*)(vtabT + l * 220);
#pragma unroll
        for (int t4 = 0; t4 < 54; t4++) {
            float4 a = sb4[t4], vv = vt4[t4];
            acc += a.x * vv.x + a.y * vv.y + a.z * vv.z + a.w * vv.w;
        }
        g_att[(tok0 + i) * 256 + h * 32 + l] = acc;
    }
}

// ---------------------------------------------------------------------------
extern "C" void kernel_launch(void* const* d_in, const int* in_sizes, int n_in,
                              void* d_out, int out_size)
{
    const float* feats    = (const float*)d_in[0];
    const float* n_coords = (const float*)d_in[1];
    const float* qkv_w    = (const float*)d_in[2];
    const float* qkv_b    = (const float*)d_in[3];
    const float* qx       = (const float*)d_in[4];
    const float* kx       = (const float*)d_in[5];
    const float* vx       = (const float*)d_in[6];
    const float* qr       = (const float*)d_in[7];
    const float* kr       = (const float*)d_in[8];
    const float* vr       = (const float*)d_in[9];
    const float* pw       = (const float*)d_in[10];
    const float* pb       = (const float*)d_in[11];
    float* out = (float*)d_out;

    cudaFuncSetAttribute(attn_kernel,
                         cudaFuncAttributeMaxDynamicSharedMemorySize,
                         SMEM_BYTES);

    qkv_gemm_kernel<<<dim3(128, 12), 256>>>(feats, qkv_w, qkv_b);
    attn_kernel<<<dim3(NW, HH), 256, SMEM_BYTES>>>(n_coords, qx, kx, vx,
                                                   qr, kr, vr);
    proj_gemm_kernel<<<dim3(128, 4), 256>>>(pw, pb, out);
}

// round 4
// speedup vs baseline: 1.5559x; 1.5559x over previous
#include <cuda_runtime.h>
#include <cuda_bf16.h>
#include <math.h>

// Problem constants
#define NTOK   8192
#define DIM    256
#define HH     8
#define HD     32
#define WW     64
#define NW     128          // NTOK / WW
#define T6     216          // 3*40 + 3*32
#define QSCALE 0.17677669529663687f   // 32^-0.5

typedef unsigned long long u64;

// ---- packed f32x2 helpers (sm_100+) ----
__device__ __forceinline__ void ffma2(u64 &c, u64 a, u64 b) {
    asm("fma.rn.f32x2 %0, %1, %2, %0;" : "+l"(c) : "l"(a), "l"(b));
}
__device__ __forceinline__ u64 pk2(float lo, float hi) {
    u64 r; asm("mov.b64 %0, {%1, %2};" : "=l"(r) : "f"(lo), "f"(hi)); return r;
}
__device__ __forceinline__ float2 up2(u64 v) {
    float2 r; asm("mov.b64 {%0, %1}, %2;" : "=f"(r.x), "=f"(r.y) : "l"(v)); return r;
}
__device__ __forceinline__ float hsum2(u64 v) { float2 p = up2(v); return p.x + p.y; }

// Global scratch (static device allocations -- allowed)
__device__ float g_q[NTOK * DIM];
__device__ float g_k[NTOK * DIM];
__device__ float g_v[NTOK * DIM];
__device__ float g_att[NTOK * DIM];

// ---------------------------------------------------------------------------
// QKV GEMM: qkv = feats[8192,256] @ qkv_w^T[256,768] + b -> split q(scaled)/k/v
// BM=128 BN=128 BK=16, 256 threads, 8x8 per thread via f32x2.
// ---------------------------------------------------------------------------
__global__ __launch_bounds__(256) void qkv_gemm_kernel(
    const float* __restrict__ A, const float* __restrict__ Wt,
    const float* __restrict__ bias)
{
    __shared__ __align__(16) float As[16][132];
    __shared__ __align__(16) float Bs[16][132];
    const int m0 = blockIdx.x * 128, n0 = blockIdx.y * 128;
    const int tid = threadIdx.x;
    const int tx = tid & 15, ty = tid >> 4;
    const int lr = tid >> 1, lc = (tid & 1) * 8;

    u64 c2[8][4];
#pragma unroll
    for (int i = 0; i < 8; i++)
#pragma unroll
        for (int j = 0; j < 4; j++) c2[i][j] = pk2(0.f, 0.f);

    const float* Arow = A  + (m0 + lr) * 256 + lc;
    const float* Brow = Wt + (n0 + lr) * 256 + lc;

    for (int kk = 0; kk < 256; kk += 16) {
        float4 a0 = *(const float4*)(Arow + kk);
        float4 a1 = *(const float4*)(Arow + kk + 4);
        float4 b0 = *(const float4*)(Brow + kk);
        float4 b1 = *(const float4*)(Brow + kk + 4);
        __syncthreads();
        As[lc + 0][lr] = a0.x; As[lc + 1][lr] = a0.y;
        As[lc + 2][lr] = a0.z; As[lc + 3][lr] = a0.w;
        As[lc + 4][lr] = a1.x; As[lc + 5][lr] = a1.y;
        As[lc + 6][lr] = a1.z; As[lc + 7][lr] = a1.w;
        Bs[lc + 0][lr] = b0.x; Bs[lc + 1][lr] = b0.y;
        Bs[lc + 2][lr] = b0.z; Bs[lc + 3][lr] = b0.w;
        Bs[lc + 4][lr] = b1.x; Bs[lc + 5][lr] = b1.y;
        Bs[lc + 6][lr] = b1.z; Bs[lc + 7][lr] = b1.w;
        __syncthreads();
#pragma unroll
        for (int k = 0; k < 16; k++) {
            float4 av0 = *(const float4*)&As[k][ty * 4];
            float4 av1 = *(const float4*)&As[k][64 + ty * 4];
            ulonglong2 bl = *(const ulonglong2*)&Bs[k][tx * 4];
            ulonglong2 bh = *(const ulonglong2*)&Bs[k][64 + tx * 4];
            u64 bb[4] = {bl.x, bl.y, bh.x, bh.y};
            float aa[8] = {av0.x, av0.y, av0.z, av0.w,
                           av1.x, av1.y, av1.z, av1.w};
#pragma unroll
            for (int i = 0; i < 8; i++) {
                u64 ad = pk2(aa[i], aa[i]);
#pragma unroll
                for (int j = 0; j < 4; j++) ffma2(c2[i][j], ad, bb[j]);
            }
        }
    }

#pragma unroll
    for (int i = 0; i < 8; i++) {
        int m = m0 + ((i < 4) ? (ty * 4 + i) : (64 + ty * 4 + i - 4));
#pragma unroll
        for (int g = 0; g < 2; g++) {
            int n = n0 + g * 64 + tx * 4;
            float2 p0 = up2(c2[i][g * 2]);
            float2 p1 = up2(c2[i][g * 2 + 1]);
            float4 b4 = *(const float4*)&bias[n];
            float4 o;
            o.x = p0.x + b4.x; o.y = p0.y + b4.y;
            o.z = p1.x + b4.z; o.w = p1.y + b4.w;
            int s = n >> 8, col = n & 255;
            float* dst;
            if (s == 0) {
                o.x *= QSCALE; o.y *= QSCALE; o.z *= QSCALE; o.w *= QSCALE;
                dst = g_q;
            } else if (s == 1) dst = g_k;
            else               dst = g_v;
            *(float4*)&dst[m * 256 + col] = o;
        }
    }
}

// ---------------------------------------------------------------------------
// Projection GEMM: out = g_att[8192,256] @ proj_w^T[256,256] + proj_b
// ---------------------------------------------------------------------------
__global__ __launch_bounds__(256) void proj_gemm_kernel(
    const float* __restrict__ Wt, const float* __restrict__ bias,
    float* __restrict__ out)
{
    __shared__ __align__(16) float As[16][132];
    __shared__ __align__(16) float Bs[16][132];
    const int m0 = blockIdx.x * 128, n0 = blockIdx.y * 128;
    const int tid = threadIdx.x;
    const int tx = tid & 15, ty = tid >> 4;
    const int lr = tid >> 1, lc = (tid & 1) * 8;

    u64 c2[8][4];
#pragma unroll
    for (int i = 0; i < 8; i++)
#pragma unroll
        for (int j = 0; j < 4; j++) c2[i][j] = pk2(0.f, 0.f);

    const float* Arow = g_att + (m0 + lr) * 256 + lc;
    const float* Brow = Wt    + (n0 + lr) * 256 + lc;

    for (int kk = 0; kk < 256; kk += 16) {
        float4 a0 = *(const float4*)(Arow + kk);
        float4 a1 = *(const float4*)(Arow + kk + 4);
        float4 b0 = *(const float4*)(Brow + kk);
        float4 b1 = *(const float4*)(Brow + kk + 4);
        __syncthreads();
        As[lc + 0][lr] = a0.x; As[lc + 1][lr] = a0.y;
        As[lc + 2][lr] = a0.z; As[lc + 3][lr] = a0.w;
        As[lc + 4][lr] = a1.x; As[lc + 5][lr] = a1.y;
        As[lc + 6][lr] = a1.z; As[lc + 7][lr] = a1.w;
        Bs[lc + 0][lr] = b0.x; Bs[lc + 1][lr] = b0.y;
        Bs[lc + 2][lr] = b0.z; Bs[lc + 3][lr] = b0.w;
        Bs[lc + 4][lr] = b1.x; Bs[lc + 5][lr] = b1.y;
        Bs[lc + 6][lr] = b1.z; Bs[lc + 7][lr] = b1.w;
        __syncthreads();
#pragma unroll
        for (int k = 0; k < 16; k++) {
            float4 av0 = *(const float4*)&As[k][ty * 4];
            float4 av1 = *(const float4*)&As[k][64 + ty * 4];
            ulonglong2 bl = *(const ulonglong2*)&Bs[k][tx * 4];
            ulonglong2 bh = *(const ulonglong2*)&Bs[k][64 + tx * 4];
            u64 bb[4] = {bl.x, bl.y, bh.x, bh.y};
            float aa[8] = {av0.x, av0.y, av0.z, av0.w,
                           av1.x, av1.y, av1.z, av1.w};
#pragma unroll
            for (int i = 0; i < 8; i++) {
                u64 ad = pk2(aa[i], aa[i]);
#pragma unroll
                for (int j = 0; j < 4; j++) ffma2(c2[i][j], ad, bb[j]);
            }
        }
    }

#pragma unroll
    for (int i = 0; i < 8; i++) {
        int m = m0 + ((i < 4) ? (ty * 4 + i) : (64 + ty * 4 + i - 4));
#pragma unroll
        for (int g = 0; g < 2; g++) {
            int n = n0 + g * 64 + tx * 4;
            float2 p0 = up2(c2[i][g * 2]);
            float2 p1 = up2(c2[i][g * 2 + 1]);
            float4 b4 = *(const float4*)&bias[n];
            float4 o;
            o.x = p0.x + b4.x; o.y = p0.y + b4.y;
            o.z = p1.x + b4.z; o.w = p1.y + b4.w;
            *(float4*)&out[m * 256 + n] = o;
        }
    }
}

// ---------------------------------------------------------------------------
// Attention kernel: one block per (window, head). 512 threads (16 warps).
// Shared layout (floats), total 53248 floats = 212992 B:
//   scw   [64*6]    @ 0
//   sq    [64*36]   @ 384
//   sk    [64*36]   @ 2688
//   svT   [32*68]   @ 4992     (d-major)
//   stabQ [216*32]  @ 7168     (dead after Dq/Dk; vtabT aliases @7168 str 220)
//   stabK [216*32]  @ 14080
//   sdq   [64*220]  @ 20992    (dead after logits; sat aliases, str 220)
//   sdk   [64*220]  @ 35072
//   slog  [64*64]   @ 49152
// ---------------------------------------------------------------------------
#define SM_FLOATS 53248
#define SMEM_BYTES (SM_FLOATS * 4)

__global__ __launch_bounds__(512) void attn_kernel(
    const float* __restrict__ n_coords,
    const float* __restrict__ qx, const float* __restrict__ kx,
    const float* __restrict__ vx,
    const float* __restrict__ qr, const float* __restrict__ kr,
    const float* __restrict__ vr)
{
    extern __shared__ __align__(16) float sm[];
    float* scw   = sm;
    float* sq    = sm + 384;
    float* sk    = sm + 2688;
    float* svT   = sm + 4992;
    float* stabQ = sm + 7168;
    float* stabK = sm + 14080;
    float* sdq   = sm + 20992;  // stride 220
    float* sdk   = sm + 35072;  // stride 220
    float* slog  = sm + 49152;
    float* sat   = sdq;         // stride 220, aliases after logits
    float* vtabT = stabQ;       // 32 rows, stride 220, aliases after Dq/Dk

    const int nb = blockIdx.x, h = blockIdx.y;
    const int tid = threadIdx.x;
    const int l = tid & 31, w = tid >> 5;
    const int tok0 = nb * WW;

    // ---- load coords, q, k, v(T), both tables ----
    for (int s = tid; s < WW * 6; s += 512) {
        int i = s / 6, c = s % 6;
        scw[s] = n_coords[(tok0 + i) * 6 + c] * (c < 3 ? 4.0f : 8.0f);
    }
    for (int s = tid; s < WW * HD; s += 512) {
        int i = s >> 5, d = s & 31;
        int g = (tok0 + i) * 256 + h * 32 + d;
        sq[i * 36 + d]  = g_q[g];
        sk[i * 36 + d]  = g_k[g];
        svT[d * 68 + i] = g_v[g];
    }
    for (int s = tid; s < T6 * HD; s += 512) {
        int t = s >> 5, d = s & 31;
        stabQ[s] = (t < 120) ? qx[(t * 8 + h) * 32 + d]
                             : qr[((t - 120) * 8 + h) * 32 + d];
        stabK[s] = (t < 120) ? kx[(t * 8 + h) * 32 + d]
                             : kr[((t - 120) * 8 + h) * 32 + d];
    }
    __syncthreads();

    // ---- Dq / Dk : 512 threads, i = tid&63, each group covers 27 t ----
    {
        const int i = tid & 63, grp = tid >> 6;
        const int t0 = grp * 27, t1 = t0 + 27;
        {
            const ulonglong2* q2p = (const ulonglong2*)(sq + i * 36);
            ulonglong2 a2[8];
#pragma unroll
            for (int d2 = 0; d2 < 8; d2++) a2[d2] = q2p[d2];
            for (int t = t0; t < t1; t++) {
                const ulonglong2* tv = (const ulonglong2*)(stabQ + t * 32);
                u64 acc = pk2(0.f, 0.f);
#pragma unroll
                for (int d2 = 0; d2 < 8; d2++) {
                    ulonglong2 tvv = tv[d2];
                    ffma2(acc, a2[d2].x, tvv.x);
                    ffma2(acc, a2[d2].y, tvv.y);
                }
                sdq[i * 220 + t] = hsum2(acc);
            }
        }
        {
            const ulonglong2* k2p = (const ulonglong2*)(sk + i * 36);
            ulonglong2 a2[8];
#pragma unroll
            for (int d2 = 0; d2 < 8; d2++) a2[d2] = k2p[d2];
            for (int t = t0; t < t1; t++) {
                const ulonglong2* tv = (const ulonglong2*)(stabK + t * 32);
                u64 acc = pk2(0.f, 0.f);
#pragma unroll
                for (int d2 = 0; d2 < 8; d2++) {
                    ulonglong2 tvv = tv[d2];
                    ffma2(acc, a2[d2].x, tvv.x);
                    ffma2(acc, a2[d2].y, tvv.y);
                }
                sdk[i * 220 + t] = hsum2(acc);
            }
        }
    }
    __syncthreads();

    // ---- logits (4 rows per warp) + softmax ----
    {
        const int basec[6] = {0, 40, 80, 120, 152, 184};
        const int offc[6]  = {20, 20, 20, 16, 16, 16};
        const int hic[6]   = {39, 39, 39, 31, 31, 31};
#pragma unroll
        for (int r = 0; r < 4; r++) {
            int i = w * 4 + r;
            float ci[6];
#pragma unroll
            for (int c = 0; c < 6; c++) ci[c] = scw[i * 6 + c];
            const ulonglong2* q2p = (const ulonglong2*)(sq + i * 36);
            ulonglong2 q2[8];
#pragma unroll
            for (int d2 = 0; d2 < 8; d2++) q2[d2] = q2p[d2];
#pragma unroll
            for (int jj = 0; jj < 2; jj++) {
                int j = l + jj * 32;
                const ulonglong2* k2p = (const ulonglong2*)(sk + j * 36);
                u64 acc2 = pk2(0.f, 0.f);
#pragma unroll
                for (int d2 = 0; d2 < 8; d2++) {
                    ulonglong2 kv = k2p[d2];
                    ffma2(acc2, q2[d2].x, kv.x);
                    ffma2(acc2, q2[d2].y, kv.y);
                }
                float acc = hsum2(acc2);
#pragma unroll
                for (int c = 0; c < 6; c++) {
                    int id = (int)floorf(ci[c] - scw[j * 6 + c]) + offc[c];
                    id = min(max(id, 0), hic[c]);
                    int t = basec[c] + id;
                    acc += sdq[i * 220 + t] + sdk[j * 220 + t];
                }
                slog[i * 64 + j] = acc;
            }
        }
    }
    // softmax: each warp owns its 4 rows (writer lanes == reader lanes)
#pragma unroll
    for (int r = 0; r < 4; r++) {
        int i = w * 4 + r;
        float v0 = slog[i * 64 + l], v1 = slog[i * 64 + l + 32];
        float m = fmaxf(v0, v1);
#pragma unroll
        for (int o = 16; o > 0; o >>= 1)
            m = fmaxf(m, __shfl_xor_sync(0xffffffffu, m, o));
        float e0 = __expf(v0 - m), e1 = __expf(v1 - m);
        float s = e0 + e1;
#pragma unroll
        for (int o = 16; o > 0; o >>= 1)
            s += __shfl_xor_sync(0xffffffffu, s, o);
        float inv = 1.0f / s;
        slog[i * 64 + l]      = e0 * inv;
        slog[i * 64 + l + 32] = e1 * inv;
    }
    __syncthreads();   // all warps done with sdq/sdk/stab before aliasing

    // ---- zero bins, load v-table (transposed) into stab region ----
    for (int s = tid; s < 64 * 220; s += 512) sat[s] = 0.f;
    for (int s = tid; s < T6 * HD; s += 512) {
        int t = s >> 5, d = s & 31;
        float val = (t < 120) ? vx[(t * 8 + h) * 32 + d]
                              : vr[((t - 120) * 8 + h) * 32 + d];
        vtabT[d * 220 + t] = val;
    }
    __syncthreads();

    // ---- bin attn into at[i][t6] (own rows per warp; shared atomics) ----
    {
        const int basec[6] = {0, 40, 80, 120, 152, 184};
        const int offc[6]  = {20, 20, 20, 16, 16, 16};
        const int hic[6]   = {39, 39, 39, 31, 31, 31};
#pragma unroll
        for (int r = 0; r < 4; r++) {
            int i = w * 4 + r;
            float ci[6];
#pragma unroll
            for (int c = 0; c < 6; c++) ci[c] = scw[i * 6 + c];
#pragma unroll
            for (int jj = 0; jj < 2; jj++) {
                int j = l + jj * 32;
                float a = slog[i * 64 + j];
#pragma unroll
                for (int c = 0; c < 6; c++) {
                    int id = (int)floorf(ci[c] - scw[j * 6 + c]) + offc[c];
                    id = min(max(id, 0), hic[c]);
                    atomicAdd(&sat[i * 220 + basec[c] + id], a);
                }
            }
        }
    }
    __syncwarp();   // bins of this warp's rows visible warp-wide

    // ---- out[i][d] = attn @ v + at @ vtab ; lane = d, v chunks reused x4 rows
    {
        const int i0 = w * 4;
        u64 acc2[4];
#pragma unroll
        for (int r = 0; r < 4; r++) acc2[r] = pk2(0.f, 0.f);

        const ulonglong2* v2p = (const ulonglong2*)(svT + l * 68);
#pragma unroll
        for (int j4 = 0; j4 < 16; j4++) {
            ulonglong2 v2 = v2p[j4];
#pragma unroll
            for (int r = 0; r < 4; r++) {
                ulonglong2 a2 = *(const ulonglong2*)&slog[(i0 + r) * 64 + j4 * 4];
                ffma2(acc2[r], a2.x, v2.x);
                ffma2(acc2[r], a2.y, v2.y);
            }
        }
        const ulonglong2* vt2p = (const ulonglong2*)(vtabT + l * 220);
#pragma unroll
        for (int t4 = 0; t4 < 54; t4++) {
            ulonglong2 v2 = vt2p[t4];
#pragma unroll
            for (int r = 0; r < 4; r++) {
                ulonglong2 a2 = *(const ulonglong2*)&sat[(i0 + r) * 220 + t4 * 4];
                ffma2(acc2[r], a2.x, v2.x);
                ffma2(acc2[r], a2.y, v2.y);
            }
        }
#pragma unroll
        for (int r = 0; r < 4; r++)
            g_att[(tok0 + i0 + r) * 256 + h * 32 + l] = hsum2(acc2[r]);
    }
}

// ---------------------------------------------------------------------------
extern "C" void kernel_launch(void* const* d_in, const int* in_sizes, int n_in,
                              void* d_out, int out_size)
{
    const float* feats    = (const float*)d_in[0];
    const float* n_coords = (const float*)d_in[1];
    const float* qkv_w    = (const float*)d_in[2];
    const float* qkv_b    = (const float*)d_in[3];
    const float* qx       = (const float*)d_in[4];
    const float* kx       = (const float*)d_in[5];
    const float* vx       = (const float*)d_in[6];
    const float* qr       = (const float*)d_in[7];
    const float* kr       = (const float*)d_in[8];
    const float* vr       = (const float*)d_in[9];
    const float* pw       = (const float*)d_in[10];
    const float* pb       = (const float*)d_in[11];
    float* out = (float*)d_out;

    cudaFuncSetAttribute(attn_kernel,
                         cudaFuncAttributeMaxDynamicSharedMemorySize,
                         SMEM_BYTES);

    qkv_gemm_kernel<<<dim3(64, 6), 256>>>(feats, qkv_w, qkv_b);
    attn_kernel<<<dim3(NW, HH), 512, SMEM_BYTES>>>(n_coords, qx, kx, vx,
                                                   qr, kr, vr);
    proj_gemm_kernel<<<dim3(64, 2), 256>>>(pw, pb, out);
}